// round 14
// baseline (speedup 1.0000x reference)
#include <cuda_runtime.h>
#include <cuda_fp16.h>
#include <cstdint>

#define BATCH 8
#define NSEQ  4096
#define DD    512
#define MROWS (BATCH * NSEQ)   // 32768

// ---------------- scratch (__device__ globals; allocation-free rule) -------
__device__ __half g_aH[MROWS * DD];        // fp16(a)
__device__ __half g_bH[MROWS * DD];        // fp16(b)
__device__ __half g_kH[MROWS * DD];        // fp16(normalized K)
__device__ __half g_tH[MROWS * DD];        // fp16(T)
__device__ __half g_WHq[DD * DD], g_WHk[DD * DD], g_WHf[DD * DD];
__device__ __half g_WpB[BATCH][DD * DD];   // fp16(Wp * diag(G[b]))
__device__ float g_Q[MROWS * DD];
__device__ float g_K[MROWS * DD];
__device__ float g_A[MROWS];
__device__ float g_nA[BATCH];              // sum of A^2 per batch (atomic)
__device__ float g_G[BATCH * DD];
__device__ float g_Gp[8][BATCH * DD];

__device__ __forceinline__ uint32_t s2u(const void* p) {
    uint32_t a;
    asm("{ .reg .u64 t; cvta.to.shared.u64 t, %1; cvt.u32.u64 %0, t; }"
        : "=r"(a) : "l"(p));
    return a;
}
__device__ __forceinline__ unsigned short us(__half h) {
    return __half_as_ushort(h);
}
__device__ __forceinline__ uint32_t pk(__half a, __half b) {
    return (uint32_t)us(a) | ((uint32_t)us(b) << 16);
}

#define MMA_F16(d, a, b)                                                     \
    asm volatile(                                                            \
        "mma.sync.aligned.m16n8k16.row.col.f32.f16.f16.f32 "                 \
        "{%0,%1,%2,%3},{%4,%5,%6,%7},{%8,%9},{%0,%1,%2,%3};"                 \
        : "+f"(d[0]), "+f"(d[1]), "+f"(d[2]), "+f"(d[3])                     \
        : "r"(a[0]), "r"(a[1]), "r"(a[2]), "r"(a[3]), "r"(b[0]), "r"(b[1]))

#define LDSM4(r0, r1, r2, r3, addr)                                          \
    asm volatile("ldmatrix.sync.aligned.m8n8.x4.shared.b16 {%0,%1,%2,%3}, [%4];" \
                 : "=r"(r0), "=r"(r1), "=r"(r2), "=r"(r3) : "r"(addr))

#define CP16(dst, src)                                                       \
    asm volatile("cp.async.ca.shared.global [%0], [%1], 16;"                 \
                 :: "r"(dst), "l"(src))
#define CP_COMMIT() asm volatile("cp.async.commit_group;" ::: "memory")
#define CP_WAIT2()  asm volatile("cp.async.wait_group 2;" ::: "memory")

// ---------------- tensor-core GEMM: plain fp16, ldmatrix frags -------------
// C[m,n] = sum_k A[m,k]*W[n,k] + bias (+residual). A, W pre-rounded fp16.
// Block 128x128, BK=32 (2 x 16-k subtiles), 8 warps (4m x 2n), warp 32x64.
// smem/stage: 2 planes (A, W), each 2 subtiles x 128 rows x 24 halves
// (16 data + 8 pad -> 48B stride: conflict-free for ldmatrix row fetches).
// 4-buffer cp.async pipeline, ONE __syncthreads per stage.
// Fragments via ldmatrix.x4: 2 (A) + 4 (B) per 16-k subtile; register
// contents bit-identical to the scalar-LDS scheme of R13.
constexpr int SUB_B   = 128 * 48;          // 6144 B per 16-k subtile plane
constexpr int PLANE_B = 2 * SUB_B;         // 12288
constexpr int STAGE_B = 2 * PLANE_B;       // 24576
constexpr int HDR     = 2048;
constexpr int SMEM_TOTAL = HDR + 4 * STAGE_B;   // 100352 B
constexpr int NSTG = 16;                   // K = 512 / 32

// CFG: 0: A=g_aH, W=WHq,        out fp32 g_Q  (+bq)
//      1: A=g_bH, W=WHk,        out fp32 g_K  (+bk)
//      2: A=g_kH, W=WpB[batch], out fp16 g_tH (+bp + g_Q residual)
//      3: A=g_tH, W=WHf,        out fp32 outf (+bf)
template<int CFG>
__global__ __launch_bounds__(256)
void gemm9(const float* __restrict__ bias, float* __restrict__ outf)
{
    const int m0 = blockIdx.y * 128, n0 = blockIdx.x * 128;
    const __half* Ah_ = (CFG == 0) ? g_aH : (CFG == 1) ? g_bH : (CFG == 2) ? g_kH : g_tH;
    const __half* Wh_ = (CFG == 0) ? g_WHq : (CFG == 1) ? g_WHk
                       : (CFG == 2) ? g_WpB[m0 >> 12] : g_WHf;

    extern __shared__ char smem[];
    const int t = threadIdx.x, lane = t & 31, w = t >> 5;
    const int wm = (w >> 1) * 32, wn = (w & 1) * 64;
    const int g = lane >> 2, tg = lane & 3;

    if (t < 128) ((float*)smem)[t] = bias[n0 + t];

    const uint32_t sbase = s2u(smem) + HDR;

    // ldmatrix per-lane offsets (within a plane/subtile)
    const int aoff = (wm + (lane & 15)) * 48 + (lane >> 4) * 16;
    const int rB   = (lane & 7) + ((lane >> 4) << 3);
    const int khB  = (lane >> 3) & 1;
    const int boff = (wn + rB) * 48 + khB * 16;

    auto fill = [&](int s, int buf) {
        uint32_t bp = sbase + buf * STAGE_B;
        #pragma unroll
        for (int i = 0; i < 4; i++) {
            const int plane = i >> 1;
            const int p = (i & 1) * 256 + t;
            const int row = p >> 2, sub = (p >> 1) & 1, cc = p & 1;
            const __half* gp = (plane == 0) ? Ah_ : Wh_;
            const int rbase = (plane == 0) ? m0 : n0;
            const void* src = gp + (rbase + row) * DD + s * 32 + sub * 16 + cc * 8;
            uint32_t dst = bp + plane * PLANE_B + sub * SUB_B + row * 48 + cc * 16;
            CP16(dst, src);
        }
    };

    float c[2][8][4] = {};

    fill(0, 0); CP_COMMIT();
    fill(1, 1); CP_COMMIT();
    fill(2, 2); CP_COMMIT();

    for (int s = 0; s < NSTG; s++) {
        CP_WAIT2();
        __syncthreads();
        if (s + 3 < NSTG) fill(s + 3, (s + 3) & 3);
        CP_COMMIT();

        const uint32_t sb = sbase + (s & 3) * STAGE_B;
        #pragma unroll
        for (int kk = 0; kk < 2; kk++) {
            const uint32_t aB = sb + kk * SUB_B;
            const uint32_t bB = sb + PLANE_B + kk * SUB_B;

            uint32_t ah[2][4], bh[8][2];
            #pragma unroll
            for (int i = 0; i < 2; i++)
                LDSM4(ah[i][0], ah[i][1], ah[i][2], ah[i][3],
                      aB + aoff + i * (16 * 48));
            #pragma unroll
            for (int jj = 0; jj < 4; jj++)
                LDSM4(bh[2 * jj][0], bh[2 * jj][1], bh[2 * jj + 1][0], bh[2 * jj + 1][1],
                      bB + boff + jj * (16 * 48));

            #pragma unroll
            for (int i = 0; i < 2; i++)
                #pragma unroll
                for (int j = 0; j < 8; j++)
                    MMA_F16(c[i][j], ah[i], bh[j]);
        }
    }

    __syncthreads();   // protect bias smem reads below (paranoia) & drain

    // Epilogue
    const float* sbias = (const float*)smem;
    #pragma unroll
    for (int i = 0; i < 2; i++) {
        #pragma unroll
        for (int j = 0; j < 8; j++) {
            int rm = m0 + wm + i * 16 + g;
            int cn = n0 + wn + j * 8 + 2 * tg;
            float2 bb = *(const float2*)&sbias[cn - n0];
            float v00 = c[i][j][0] + bb.x, v01 = c[i][j][1] + bb.y;
            float v10 = c[i][j][2] + bb.x, v11 = c[i][j][3] + bb.y;
            if (CFG != 2) {
                float* Cp = (CFG == 0) ? g_Q : (CFG == 1) ? g_K : outf;
                *(float2*)&Cp[rm * DD + cn]       = make_float2(v00, v01);
                *(float2*)&Cp[(rm + 8) * DD + cn] = make_float2(v10, v11);
            } else {
                float2 r0 = *(const float2*)&g_Q[rm * DD + cn];
                float2 r1 = *(const float2*)&g_Q[(rm + 8) * DD + cn];
                v00 += r0.x; v01 += r0.y; v10 += r1.x; v11 += r1.y;
                *(uint32_t*)&g_tH[rm * DD + cn] =
                    pk(__float2half_rn(v00), __float2half_rn(v01));
                *(uint32_t*)&g_tH[(rm + 8) * DD + cn] =
                    pk(__float2half_rn(v10), __float2half_rn(v11));
            }
        }
    }
}

// ---------------- preprocessing: one flat kernel ---------------------------
// Rounds a, b, Wq, Wk, Wf to fp16 and zeroes g_nA. Flat float4 index space:
// [0,IN4) -> a, [IN4,2*IN4) -> b, then 3 weight matrices of W4 each.
constexpr int IN4 = MROWS * DD / 4;   // 4,194,304
constexpr int W4  = DD * DD / 4;      // 65,536

__global__ __launch_bounds__(256)
void roundall(const float4* __restrict__ a, const float4* __restrict__ b,
              const float4* __restrict__ Wq, const float4* __restrict__ Wk,
              const float4* __restrict__ Wf)
{
    int idx = blockIdx.x * 256 + threadIdx.x;
    if (blockIdx.x == 0 && threadIdx.x < BATCH) g_nA[threadIdx.x] = 0.0f;

    const float4* src;
    __half* dst;
    int off;
    if (idx < IN4)            { src = a;  dst = g_aH; off = idx; }
    else if (idx < 2 * IN4)   { src = b;  dst = g_bH; off = idx - IN4; }
    else {
        int j = idx - 2 * IN4;
        int sel = j >> 14;              // j / W4 (W4 = 16384? no: 65536/4...)
        // W4 = 65536 float4 -> sel = j / 65536
        sel = j >> 16;
        off = j & (65536 - 1);
        src = (sel == 0) ? Wq : (sel == 1) ? Wk : Wf;
        dst = (sel == 0) ? g_WHq : (sel == 1) ? g_WHk : g_WHf;
    }
    float4 v = src[off];
    ((uint2*)dst)[off] = make_uint2(pk(__float2half_rn(v.x), __float2half_rn(v.y)),
                                    pk(__float2half_rn(v.z), __float2half_rn(v.w)));
}

// WpB[b] = fp16(Wp * diag(G[b])) ; grid (W4/256, BATCH), block 256
__global__ __launch_bounds__(256)
void wpscale(const float4* __restrict__ Wp)
{
    int b = blockIdx.y;
    int i = blockIdx.x * 256 + threadIdx.x;   // float4 index
    int d = (i * 4) & (DD - 1);
    float4 v = Wp[i];
    float4 gv = *(const float4*)&g_G[b * DD + d];
    ((uint2*)g_WpB[b])[i] =
        make_uint2(pk(__float2half_rn(v.x * gv.x), __float2half_rn(v.y * gv.y)),
                   pk(__float2half_rn(v.z * gv.z), __float2half_rn(v.w * gv.w)));
}

// ---------------- l2norm + score + K fp16 ----------------------------------
__global__ __launch_bounds__(128)
void l2norm_ascore(const float* __restrict__ wg)
{
    int rowg = blockIdx.x;
    bool isQ = rowg < MROWS;
    int r = isQ ? rowg : rowg - MROWS;
    const float* X = isQ ? g_Q : g_K;

    float4 v = *((const float4*)&X[r * DD] + threadIdx.x);
    float s = v.x * v.x + v.y * v.y + v.z * v.z + v.w * v.w;
    #pragma unroll
    for (int off = 16; off > 0; off >>= 1)
        s += __shfl_xor_sync(0xFFFFFFFFu, s, off);

    __shared__ float ws[4];
    int lane = threadIdx.x & 31, wid = threadIdx.x >> 5;
    if (lane == 0) ws[wid] = s;
    __syncthreads();
    float tot = ws[0] + ws[1] + ws[2] + ws[3];
    float inv = 1.0f / fmaxf(sqrtf(tot), 1e-12f);

    v.x *= inv; v.y *= inv; v.z *= inv; v.w *= inv;

    if (isQ) {
        *((float4*)&g_Q[r * DD] + threadIdx.x) = v;
        const float4* wv = reinterpret_cast<const float4*>(wg);
        float4 wq = wv[threadIdx.x];
        float s2 = v.x * wq.x + v.y * wq.y + v.z * wq.z + v.w * wq.w;
        #pragma unroll
        for (int off = 16; off > 0; off >>= 1)
            s2 += __shfl_xor_sync(0xFFFFFFFFu, s2, off);
        __syncthreads();
        if (lane == 0) ws[wid] = s2;
        __syncthreads();
        if (threadIdx.x == 0)
            g_A[r] = (ws[0] + ws[1] + ws[2] + ws[3]) * 4.419417382415922e-2f;
    } else {
        int o = r * DD + threadIdx.x * 4;
        *(uint2*)&g_kH[o] =
            make_uint2(pk(__float2half_rn(v.x), __float2half_rn(v.y)),
                       pk(__float2half_rn(v.z), __float2half_rn(v.w)));
    }
}

// Pooling phase 1 + fused ||A||^2 partials. grid=(4 dchunk, 8 batch, 8 nsplit)
__global__ __launch_bounds__(128)
void gpoolp()
{
    int b = blockIdx.y;
    int d = blockIdx.x * 128 + threadIdx.x;
    int ns = blockIdx.z;
    int n0 = ns * (NSEQ / 8);
    float acc = 0.0f;
    #pragma unroll 4
    for (int n = n0; n < n0 + NSEQ / 8; n++)
        acc += g_A[b * NSEQ + n] * g_Q[(b * NSEQ + n) * DD + d];
    g_Gp[ns][b * DD + d] = acc;

    if (blockIdx.x == 0) {     // one dchunk contributes the ||A||^2 partial
        float q = 0.0f;
        #pragma unroll
        for (int n = n0 + threadIdx.x; n < n0 + NSEQ / 8; n += 128) {
            float av = g_A[b * NSEQ + n];
            q += av * av;
        }
        #pragma unroll
        for (int off = 16; off > 0; off >>= 1)
            q += __shfl_xor_sync(0xFFFFFFFFu, q, off);
        __shared__ float qs[4];
        int lane = threadIdx.x & 31, wid = threadIdx.x >> 5;
        if (lane == 0) qs[wid] = q;
        __syncthreads();
        if (threadIdx.x == 0)
            atomicAdd(&g_nA[b], qs[0] + qs[1] + qs[2] + qs[3]);
    }
}

// Pooling phase 2: reduce partials, apply 1/max(||A||,eps). grid=32, blk=128.
__global__ __launch_bounds__(128)
void gpoolr()
{
    int i = blockIdx.x * 128 + threadIdx.x;
    int b = i / DD;
    float s = 0.0f;
    #pragma unroll
    for (int p = 0; p < 8; p++) s += g_Gp[p][i];
    float inv = 1.0f / fmaxf(sqrtf(g_nA[b]), 1e-12f);
    g_G[i] = s * inv;
}

// ---------------------------------------------------------------------------
extern "C" void kernel_launch(void* const* d_in, const int* in_sizes, int n_in,
                              void* d_out, int out_size)
{
    const float* a  = (const float*)d_in[0];
    const float* b  = (const float*)d_in[1];
    const float* Wq = (const float*)d_in[2];
    const float* bq = (const float*)d_in[3];
    const float* Wk = (const float*)d_in[4];
    const float* bk = (const float*)d_in[5];
    const float* wg = (const float*)d_in[6];
    const float* Wp = (const float*)d_in[7];
    const float* bp = (const float*)d_in[8];
    const float* Wf = (const float*)d_in[9];
    const float* bf = (const float*)d_in[10];
    float* out = (float*)d_out;

    cudaFuncSetAttribute(gemm9<0>, cudaFuncAttributeMaxDynamicSharedMemorySize, SMEM_TOTAL);
    cudaFuncSetAttribute(gemm9<1>, cudaFuncAttributeMaxDynamicSharedMemorySize, SMEM_TOTAL);
    cudaFuncSetAttribute(gemm9<2>, cudaFuncAttributeMaxDynamicSharedMemorySize, SMEM_TOTAL);
    cudaFuncSetAttribute(gemm9<3>, cudaFuncAttributeMaxDynamicSharedMemorySize, SMEM_TOTAL);

    const int TOT4 = 2 * IN4 + 3 * W4;
    roundall<<<TOT4 / 256, 256>>>((const float4*)a, (const float4*)b,
                                  (const float4*)Wq, (const float4*)Wk,
                                  (const float4*)Wf);

    dim3 gg(4, MROWS / 128);   // (4, 256)

    gemm9<0><<<gg, 256, SMEM_TOTAL>>>(bq, nullptr);   // Q = a@Wq^T + bq
    gemm9<1><<<gg, 256, SMEM_TOTAL>>>(bk, nullptr);   // K = b@Wk^T + bk
    l2norm_ascore<<<2 * MROWS, 128>>>(wg);
    gpoolp<<<dim3(4, BATCH, 8), 128>>>();             // + fused ||A||^2
    gpoolr<<<32, 128>>>();
    wpscale<<<dim3(W4 / 256, BATCH), 256>>>((const float4*)Wp);
    gemm9<2><<<gg, 256, SMEM_TOTAL>>>(bp, nullptr);   // T = K@(Wp*G)^T+bp+Q (fp16)
    gemm9<3><<<gg, 256, SMEM_TOTAL>>>(bf, out);       // out = T@Wf^T + bf
}

// round 15
// speedup vs baseline: 1.2421x; 1.2421x over previous
#include <cuda_runtime.h>
#include <cuda_fp16.h>
#include <cstdint>

#define BATCH 8
#define NSEQ  4096
#define DD    512
#define MROWS (BATCH * NSEQ)   // 32768

// ---------------- scratch (__device__ globals; allocation-free rule) -------
__device__ __half g_aH[MROWS * DD];        // fp16(a)
__device__ __half g_bH[MROWS * DD];        // fp16(b)
__device__ __half g_qu[MROWS * DD];        // fp16(Q unnormalized)
__device__ __half g_ku[MROWS * DD];        // fp16(K unnormalized)
__device__ __half g_tH[MROWS * DD];        // fp16(T)
__device__ __half g_WHq[DD * DD], g_WHk[DD * DD], g_WHf[DD * DD];
__device__ __half g_WpB[BATCH][DD * DD];   // fp16(Wp * diag(G[b]))
__device__ float g_sqQ[MROWS];             // per-row sum of Q^2 (atomic)
__device__ float g_sqK[MROWS];             // per-row sum of K^2 (atomic)
__device__ float g_invQ[MROWS];            // 1/max(||Q row||, eps)
__device__ float g_invK[MROWS];            // 1/max(||K row||, eps)
__device__ float g_A[MROWS];               // gating scores
__device__ float g_Ai[MROWS];              // A * invQ  (pooling weight)
__device__ float g_nA[BATCH];              // sum of A^2 per batch (atomic)
__device__ float g_G[BATCH * DD];
__device__ float g_Gp[8][BATCH * DD];

__device__ __forceinline__ uint32_t s2u(const void* p) {
    uint32_t a;
    asm("{ .reg .u64 t; cvta.to.shared.u64 t, %1; cvt.u32.u64 %0, t; }"
        : "=r"(a) : "l"(p));
    return a;
}
__device__ __forceinline__ unsigned short us(__half h) {
    return __half_as_ushort(h);
}
__device__ __forceinline__ uint32_t pk(__half a, __half b) {
    return (uint32_t)us(a) | ((uint32_t)us(b) << 16);
}
__device__ __forceinline__ float lo16(uint32_t u) {
    return __half2float(__ushort_as_half((unsigned short)(u & 0xFFFF)));
}
__device__ __forceinline__ float hi16(uint32_t u) {
    return __half2float(__ushort_as_half((unsigned short)(u >> 16)));
}

#define MMA_F16(d, a, b)                                                     \
    asm volatile(                                                            \
        "mma.sync.aligned.m16n8k16.row.col.f32.f16.f16.f32 "                 \
        "{%0,%1,%2,%3},{%4,%5,%6,%7},{%8,%9},{%0,%1,%2,%3};"                 \
        : "+f"(d[0]), "+f"(d[1]), "+f"(d[2]), "+f"(d[3])                     \
        : "r"(a[0]), "r"(a[1]), "r"(a[2]), "r"(a[3]), "r"(b[0]), "r"(b[1]))

#define CP16(dst, src)                                                       \
    asm volatile("cp.async.ca.shared.global [%0], [%1], 16;"                 \
                 :: "r"(dst), "l"(src))
#define CP_COMMIT() asm volatile("cp.async.commit_group;" ::: "memory")
#define CP_WAIT2()  asm volatile("cp.async.wait_group 2;" ::: "memory")

// ---------------- tensor-core GEMM (R13-proven core) -----------------------
// C[m,n] = sum_k A[m,k]*W[n,k] + bias (+variants). A, W fp16.
// Block 128x128, BK=32, 8 warps (4m x 2n), warp 32x64, 3-stage cp.async,
// scalar-LDS fragments on 48B-stride padded layout (conflict-free).
constexpr int SUB_B   = 128 * 48;          // 6144 B per 16-k subtile plane
constexpr int PLANE_B = 2 * SUB_B;         // 12288
constexpr int STAGE_B = 2 * PLANE_B;       // 24576
constexpr int HDR     = 2048;
constexpr int SMEM_TOTAL = HDR + 3 * STAGE_B;   // 75776 B
constexpr int NSTG = 16;                   // K = 512 / 32

// CFG 0: A=g_aH, W=WHq        -> g_qu fp16 (+bq), row sumsq -> g_sqQ
// CFG 1: A=g_bH, W=WHk        -> g_ku fp16 (+bk), row sumsq -> g_sqK
// CFG 2: A=g_ku, W=WpB[batch] -> g_tH fp16 = invK*acc + bp + invQ*Qu
// CFG 3: A=g_tH, W=WHf        -> outf fp32 (+bf)
template<int CFG>
__global__ __launch_bounds__(256)
void gemmA(const float* __restrict__ bias, float* __restrict__ outf)
{
    const int m0 = blockIdx.y * 128, n0 = blockIdx.x * 128;
    const __half* Ah_ = (CFG == 0) ? g_aH : (CFG == 1) ? g_bH : (CFG == 2) ? g_ku : g_tH;
    const __half* Wh_ = (CFG == 0) ? g_WHq : (CFG == 1) ? g_WHk
                       : (CFG == 2) ? g_WpB[m0 >> 12] : g_WHf;

    extern __shared__ char smem[];
    const int t = threadIdx.x, lane = t & 31, w = t >> 5;
    const int wm = (w >> 1) * 32, wn = (w & 1) * 64;
    const int g = lane >> 2, tg = lane & 3;

    if (t < 128) ((float*)smem)[t] = bias[n0 + t];

    const uint32_t sbase = s2u(smem) + HDR;

    auto fill = [&](int s, int buf) {
        uint32_t bp = sbase + buf * STAGE_B;
        #pragma unroll
        for (int i = 0; i < 4; i++) {
            const int plane = i >> 1;
            const int p = (i & 1) * 256 + t;
            const int row = p >> 2, sub = (p >> 1) & 1, cc = p & 1;
            const __half* gp = (plane == 0) ? Ah_ : Wh_;
            const int rbase = (plane == 0) ? m0 : n0;
            const void* src = gp + (rbase + row) * DD + s * 32 + sub * 16 + cc * 8;
            uint32_t dst = bp + plane * PLANE_B + sub * SUB_B + row * 48 + cc * 16;
            CP16(dst, src);
        }
    };

    float c[2][8][4] = {};

    fill(0, 0); CP_COMMIT();
    fill(1, 1); CP_COMMIT();

    for (int s = 0; s < NSTG; s++) {
        if (s + 2 < NSTG) fill(s + 2, (s + 2) % 3);
        CP_COMMIT();
        CP_WAIT2();
        __syncthreads();

        const uint32_t* base = (const uint32_t*)(smem + HDR + (s % 3) * STAGE_B);
        #pragma unroll
        for (int kk = 0; kk < 2; kk++) {
            const uint32_t* Awh = base + kk * (SUB_B / 4);
            const uint32_t* Bwh = Awh + PLANE_B / 4;

            uint32_t ah[2][4];
            #pragma unroll
            for (int i = 0; i < 2; i++) {
                int r = wm + i * 16 + g;
                ah[i][0] = Awh[r * 12 + tg];
                ah[i][1] = Awh[(r + 8) * 12 + tg];
                ah[i][2] = Awh[r * 12 + tg + 4];
                ah[i][3] = Awh[(r + 8) * 12 + tg + 4];
            }
            uint32_t bh[8][2];
            #pragma unroll
            for (int j = 0; j < 8; j++) {
                int nb = wn + j * 8 + g;
                bh[j][0] = Bwh[nb * 12 + tg];
                bh[j][1] = Bwh[nb * 12 + tg + 4];
            }
            #pragma unroll
            for (int i = 0; i < 2; i++)
                #pragma unroll
                for (int j = 0; j < 8; j++)
                    MMA_F16(c[i][j], ah[i], bh[j]);
        }
        __syncthreads();
    }

    // ---- Epilogue ----
    const float* sbias = (const float*)smem;
    #pragma unroll
    for (int i = 0; i < 2; i++) {
        const int rm = m0 + wm + i * 16 + g;
        float rs0 = 0.0f, rs8 = 0.0f;               // row sumsq (CFG 0/1)
        float ik0, iq0, ik8, iq8;                   // row factors (CFG 2)
        if (CFG == 2) {
            ik0 = g_invK[rm];     iq0 = g_invQ[rm];
            ik8 = g_invK[rm + 8]; iq8 = g_invQ[rm + 8];
        }
        #pragma unroll
        for (int j = 0; j < 8; j++) {
            const int cn = n0 + wn + j * 8 + 2 * tg;
            float2 bb = *(const float2*)&sbias[cn - n0];
            if (CFG == 0 || CFG == 1) {
                float v00 = c[i][j][0] + bb.x, v01 = c[i][j][1] + bb.y;
                float v10 = c[i][j][2] + bb.x, v11 = c[i][j][3] + bb.y;
                __half* D = (CFG == 0) ? g_qu : g_ku;
                *(uint32_t*)&D[rm * DD + cn] =
                    pk(__float2half_rn(v00), __float2half_rn(v01));
                *(uint32_t*)&D[(rm + 8) * DD + cn] =
                    pk(__float2half_rn(v10), __float2half_rn(v11));
                rs0 += v00 * v00 + v01 * v01;
                rs8 += v10 * v10 + v11 * v11;
            } else if (CFG == 2) {
                uint32_t q0 = *(const uint32_t*)&g_qu[rm * DD + cn];
                uint32_t q8 = *(const uint32_t*)&g_qu[(rm + 8) * DD + cn];
                float v00 = c[i][j][0] * ik0 + bb.x + iq0 * lo16(q0);
                float v01 = c[i][j][1] * ik0 + bb.y + iq0 * hi16(q0);
                float v10 = c[i][j][2] * ik8 + bb.x + iq8 * lo16(q8);
                float v11 = c[i][j][3] * ik8 + bb.y + iq8 * hi16(q8);
                *(uint32_t*)&g_tH[rm * DD + cn] =
                    pk(__float2half_rn(v00), __float2half_rn(v01));
                *(uint32_t*)&g_tH[(rm + 8) * DD + cn] =
                    pk(__float2half_rn(v10), __float2half_rn(v11));
            } else {
                *(float2*)&outf[rm * DD + cn] =
                    make_float2(c[i][j][0] + bb.x, c[i][j][1] + bb.y);
                *(float2*)&outf[(rm + 8) * DD + cn] =
                    make_float2(c[i][j][2] + bb.x, c[i][j][3] + bb.y);
            }
        }
        if (CFG == 0 || CFG == 1) {
            // reduce over tg (lanes g*4+tg): xor 1, xor 2
            rs0 += __shfl_xor_sync(0xFFFFFFFFu, rs0, 1);
            rs0 += __shfl_xor_sync(0xFFFFFFFFu, rs0, 2);
            rs8 += __shfl_xor_sync(0xFFFFFFFFu, rs8, 1);
            rs8 += __shfl_xor_sync(0xFFFFFFFFu, rs8, 2);
            if (tg == 0) {
                float* SQ = (CFG == 0) ? g_sqQ : g_sqK;
                atomicAdd(&SQ[rm], rs0);
                atomicAdd(&SQ[rm + 8], rs8);
            }
        }
    }
}

// ---------------- preprocessing: one flat kernel ---------------------------
constexpr int IN4 = MROWS * DD / 4;   // 4,194,304
constexpr int W4  = DD * DD / 4;      // 65,536

__global__ __launch_bounds__(256)
void roundall(const float4* __restrict__ a, const float4* __restrict__ b,
              const float4* __restrict__ Wq, const float4* __restrict__ Wk,
              const float4* __restrict__ Wf)
{
    int idx = blockIdx.x * 256 + threadIdx.x;
    if (idx < MROWS) {               // zero accumulators for this launch
        g_sqQ[idx] = 0.0f;
        g_sqK[idx] = 0.0f;
        if (idx < BATCH) g_nA[idx] = 0.0f;
    }

    const float4* src;
    __half* dst;
    int off;
    if (idx < IN4)            { src = a;  dst = g_aH; off = idx; }
    else if (idx < 2 * IN4)   { src = b;  dst = g_bH; off = idx - IN4; }
    else {
        int j = idx - 2 * IN4;
        int sel = j >> 16;           // / W4 (65536)
        off = j & 0xFFFF;
        src = (sel == 0) ? Wq : (sel == 1) ? Wk : Wf;
        dst = (sel == 0) ? g_WHq : (sel == 1) ? g_WHk : g_WHf;
    }
    float4 v = src[off];
    ((uint2*)dst)[off] = make_uint2(pk(__float2half_rn(v.x), __float2half_rn(v.y)),
                                    pk(__float2half_rn(v.z), __float2half_rn(v.w)));
}

// ---------------- ascore: row factors + gating scores ----------------------
// One warp per Q row: invQ = 1/max(||Qu||,eps); A = scale*invQ*dot(Qu,wg);
// Ai = A*invQ; also invK for the same row index.
__global__ __launch_bounds__(256)
void ascore(const float* __restrict__ wg)
{
    int warp = threadIdx.x >> 5, lane = threadIdx.x & 31;
    int r = blockIdx.x * 8 + warp;

    const uint2* q = (const uint2*)&g_qu[r * DD];       // 128 uint2 per row
    const float4* wv = (const float4*)wg;
    float s = 0.0f;
    #pragma unroll
    for (int i = 0; i < 4; i++) {
        uint2 u = q[lane + 32 * i];
        float4 wq = wv[lane + 32 * i];
        s += lo16(u.x) * wq.x + hi16(u.x) * wq.y
           + lo16(u.y) * wq.z + hi16(u.y) * wq.w;
    }
    #pragma unroll
    for (int off = 16; off > 0; off >>= 1)
        s += __shfl_xor_sync(0xFFFFFFFFu, s, off);

    if (lane == 0) {
        float invq = 1.0f / fmaxf(sqrtf(g_sqQ[r]), 1e-12f);
        float invk = 1.0f / fmaxf(sqrtf(g_sqK[r]), 1e-12f);
        g_invQ[r] = invq;
        g_invK[r] = invk;
        float A = s * invq * 4.419417382415922e-2f;     // 512^-0.5
        g_A[r] = A;
        g_Ai[r] = A * invq;
    }
}

// Pooling phase 1 + fused ||A||^2 partials. grid=(2 dchunk, 8 batch, 8 nsplit)
// Each thread handles 2 d's (one uint of fp16 Qu).
__global__ __launch_bounds__(128)
void gpoolp()
{
    int b = blockIdx.y;
    int d2 = blockIdx.x * 128 + threadIdx.x;   // uint index: d = 2*d2
    int ns = blockIdx.z;
    int n0 = ns * (NSEQ / 8);

    const uint32_t* qu = (const uint32_t*)g_qu;
    float acc0 = 0.0f, acc1 = 0.0f;
    #pragma unroll 4
    for (int n = n0; n < n0 + NSEQ / 8; n++) {
        float ai = g_Ai[b * NSEQ + n];
        uint32_t u = qu[(b * NSEQ + n) * (DD / 2) + d2];
        acc0 += ai * lo16(u);
        acc1 += ai * hi16(u);
    }
    g_Gp[ns][b * DD + 2 * d2]     = acc0;
    g_Gp[ns][b * DD + 2 * d2 + 1] = acc1;

    if (blockIdx.x == 0) {     // contribute this n-slice's ||A||^2 partial
        float qv = 0.0f;
        for (int n = n0 + threadIdx.x; n < n0 + NSEQ / 8; n += 128) {
            float av = g_A[b * NSEQ + n];
            qv += av * av;
        }
        #pragma unroll
        for (int off = 16; off > 0; off >>= 1)
            qv += __shfl_xor_sync(0xFFFFFFFFu, qv, off);
        __shared__ float qs[4];
        int lane = threadIdx.x & 31, wid = threadIdx.x >> 5;
        if (lane == 0) qs[wid] = qv;
        __syncthreads();
        if (threadIdx.x == 0)
            atomicAdd(&g_nA[b], qs[0] + qs[1] + qs[2] + qs[3]);
    }
}

// Pooling phase 2: reduce partials, apply 1/max(||A||,eps). grid=32, blk=128.
__global__ __launch_bounds__(128)
void gpoolr()
{
    int i = blockIdx.x * 128 + threadIdx.x;
    int b = i / DD;
    float s = 0.0f;
    #pragma unroll
    for (int p = 0; p < 8; p++) s += g_Gp[p][i];
    g_G[i] = s * (1.0f / fmaxf(sqrtf(g_nA[b]), 1e-12f));
}

// WpB[b] = fp16(Wp * diag(G[b])) ; grid (W4/256, BATCH), block 256
__global__ __launch_bounds__(256)
void wpscale(const float4* __restrict__ Wp)
{
    int b = blockIdx.y;
    int i = blockIdx.x * 256 + threadIdx.x;   // float4 index
    int d = (i * 4) & (DD - 1);
    float4 v = Wp[i];
    float4 gv = *(const float4*)&g_G[b * DD + d];
    ((uint2*)g_WpB[b])[i] =
        make_uint2(pk(__float2half_rn(v.x * gv.x), __float2half_rn(v.y * gv.y)),
                   pk(__float2half_rn(v.z * gv.z), __float2half_rn(v.w * gv.w)));
}

// ---------------------------------------------------------------------------
extern "C" void kernel_launch(void* const* d_in, const int* in_sizes, int n_in,
                              void* d_out, int out_size)
{
    const float* a  = (const float*)d_in[0];
    const float* b  = (const float*)d_in[1];
    const float* Wq = (const float*)d_in[2];
    const float* bq = (const float*)d_in[3];
    const float* Wk = (const float*)d_in[4];
    const float* bk = (const float*)d_in[5];
    const float* wg = (const float*)d_in[6];
    const float* Wp = (const float*)d_in[7];
    const float* bp = (const float*)d_in[8];
    const float* Wf = (const float*)d_in[9];
    const float* bf = (const float*)d_in[10];
    float* out = (float*)d_out;

    cudaFuncSetAttribute(gemmA<0>, cudaFuncAttributeMaxDynamicSharedMemorySize, SMEM_TOTAL);
    cudaFuncSetAttribute(gemmA<1>, cudaFuncAttributeMaxDynamicSharedMemorySize, SMEM_TOTAL);
    cudaFuncSetAttribute(gemmA<2>, cudaFuncAttributeMaxDynamicSharedMemorySize, SMEM_TOTAL);
    cudaFuncSetAttribute(gemmA<3>, cudaFuncAttributeMaxDynamicSharedMemorySize, SMEM_TOTAL);

    const int TOT4 = 2 * IN4 + 3 * W4;
    roundall<<<TOT4 / 256, 256>>>((const float4*)a, (const float4*)b,
                                  (const float4*)Wq, (const float4*)Wk,
                                  (const float4*)Wf);

    dim3 gg(4, MROWS / 128);   // (4, 256)

    gemmA<0><<<gg, 256, SMEM_TOTAL>>>(bq, nullptr);   // Qu = a@Wq^T+bq (+sumsq)
    gemmA<1><<<gg, 256, SMEM_TOTAL>>>(bk, nullptr);   // Ku = b@Wk^T+bk (+sumsq)
    ascore<<<MROWS / 8, 256>>>(wg);                   // invQ/invK/A/Ai
    gpoolp<<<dim3(2, BATCH, 8), 128>>>();             // G partials + ||A||^2
    gpoolr<<<32, 128>>>();
    wpscale<<<dim3(W4 / 256, BATCH), 256>>>((const float4*)Wp);
    gemmA<2><<<gg, 256, SMEM_TOTAL>>>(bp, nullptr);   // T (fp16, fused norm+resid)
    gemmA<3><<<gg, 256, SMEM_TOTAL>>>(bf, out);       // out = T@Wf^T + bf
}